// round 15
// baseline (speedup 1.0000x reference)
#include <cuda_runtime.h>
#include <cstdint>

#define BB 32
#define NN 8732
#define CC 21
#define N2 17464          // 2*NN
#define NV (N2/4)         // 4366 uint4s
#define TOPK 200
#define KW 7              // ceil(TOPK/32)
#define NT 512
#define NW (NT/32)
#define CAP 1024
#define STHR 40           // sampled-suffix threshold (-> ~320 est. candidates)

// scratch (allocation-free rule: device globals)
__device__ float    g_boxes[(size_t)BB * N2 * 4];   // [B][2N][4] xyxy
__device__ uint32_t g_keys[(size_t)BB * CC * N2];   // [B][C][2N] orderable keys (0 = below thresh)

__device__ __forceinline__ float o2f(uint32_t u) {
    return __uint_as_float(u & 0x7FFFFFFFu);
}
__device__ __forceinline__ unsigned long long my_u64min(unsigned long long a, unsigned long long b) {
    return a < b ? a : b;
}
__device__ __forceinline__ unsigned long long my_u64max(unsigned long long a, unsigned long long b) {
    return a > b ? a : b;
}

// ---------------------------------------------------------------------------
// Kernel 1: decode boxes (both views, view2 flipped) + softmax both views
// ---------------------------------------------------------------------------
__global__ __launch_bounds__(256) void prep_kernel(
    const float* __restrict__ loc1, const float* __restrict__ conf1,
    const float* __restrict__ loc2, const float* __restrict__ conf2,
    const float* __restrict__ dbox)
{
    int idx = blockIdx.x * 256 + threadIdx.x;
    if (idx >= BB * NN) return;
    int b = idx / NN, n = idx % NN;

    float4 d4 = ((const float4*)dbox)[n];
    float dcx = d4.x, dcy = d4.y, dw = d4.z, dh = d4.w;

    {
        float4 l = ((const float4*)loc1)[idx];
        float cx = dcx + (l.x * 0.1f) * dw;
        float cy = dcy + (l.y * 0.1f) * dh;
        float w = dw * expf(l.z * 0.2f);
        float h = dh * expf(l.w * 0.2f);
        float4 o;
        o.x = cx - w * 0.5f; o.y = cy - h * 0.5f;
        o.z = cx + w * 0.5f; o.w = cy + h * 0.5f;
        ((float4*)g_boxes)[(size_t)b * N2 + n] = o;
    }
    {
        float4 l = ((const float4*)loc2)[idx];
        float cx = dcx + (l.x * 0.1f) * dw;
        float cy = dcy + (l.y * 0.1f) * dh;
        float w = dw * expf(l.z * 0.2f);
        float h = dh * expf(l.w * 0.2f);
        float x1 = cx - w * 0.5f, x2 = cx + w * 0.5f;
        float4 o;
        o.x = 1.0f - x2; o.y = cy - h * 0.5f;
        o.z = 1.0f - x1; o.w = cy + h * 0.5f;
        ((float4*)g_boxes)[(size_t)b * N2 + NN + n] = o;
    }
    {
        const float* cf = conf1 + (size_t)idx * CC;
        float mx = cf[0];
        #pragma unroll
        for (int j = 1; j < CC; ++j) mx = fmaxf(mx, cf[j]);
        float e[CC]; float sum = 0.0f;
        #pragma unroll
        for (int j = 0; j < CC; ++j) { e[j] = expf(cf[j] - mx); sum += e[j]; }
        uint32_t* sb = g_keys + (size_t)b * CC * N2 + n;
        #pragma unroll
        for (int j = 1; j < CC; ++j) {        // class 0 never read
            float p = e[j] / sum;
            sb[(size_t)j * N2] = (p > 0.01f) ? (__float_as_uint(p) | 0x80000000u) : 0u;
        }
    }
    {
        const float* cf = conf2 + (size_t)idx * CC;
        float mx = cf[0];
        #pragma unroll
        for (int j = 1; j < CC; ++j) mx = fmaxf(mx, cf[j]);
        float e[CC]; float sum = 0.0f;
        #pragma unroll
        for (int j = 0; j < CC; ++j) { e[j] = expf(cf[j] - mx); sum += e[j]; }
        uint32_t* sb = g_keys + (size_t)b * CC * N2 + NN + n;
        #pragma unroll
        for (int j = 1; j < CC; ++j) {
            float p = e[j] / sum;
            sb[(size_t)j * N2] = (p > 0.01f) ? (__float_as_uint(p) | 0x80000000u) : 0u;
        }
    }
}

// ---------------------------------------------------------------------------
// Kernel 2: per (b, class>=1): top-200 (stable), NMS, compacted output
// ---------------------------------------------------------------------------
__global__ __launch_bounds__(NT, 4) void nms_kernel(float* __restrict__ out)
{
    const int c = blockIdx.x + 1;   // classes 1..20
    const int b = blockIdx.y;
    const int tid = threadIdx.x;
    const int lane = tid & 31, warp = tid >> 5;

    __shared__ uint32_t hist[256];
    __shared__ uint32_t wsum[8];
    __shared__ unsigned long long ck64[CAP];
    __shared__ float4 cb4[TOPK];
    __shared__ float carea[TOPK];
    __shared__ float cscore[TOPK];
    __shared__ uint32_t iou_mask[TOPK * KW];
    __shared__ int sh_bin;
    __shared__ int ccnt, eq_taken;
    __shared__ int sh_bf, sh_S, sh_Sa;
    __shared__ int warp_cnt[NW];
    __shared__ uint32_t validw[KW], keepw[KW];

    const uint32_t* su = g_keys + ((size_t)b * CC + c) * N2;
    const uint4* su4 = (const uint4*)su;
    const uint32_t gLo = (__float_as_uint(0.01f) | 0x80000000u) + 1u;  // min valid key

    // ================= sampled histogram (1/8 stride) =================
    if (tid < 256) hist[tid] = 0;
    if (tid == 0) { sh_bin = -1; ccnt = 0; eq_taken = 0; }
    __syncthreads();
    for (int i = tid; i < N2 / 8; i += NT) {
        uint32_t u = su[i << 3];
        if (u >= gLo) {
            uint32_t r = (u - gLo) >> 18;
            if (r > 255u) r = 255u;
            atomicAdd(&hist[r], 1u);
        }
    }
    __syncthreads();
    {   // inclusive suffix scan of 256 bins
        uint32_t h = (tid < 256) ? hist[tid] : 0u;
        uint32_t v = h;
        #pragma unroll
        for (int off = 1; off < 32; off <<= 1) {
            uint32_t o = __shfl_down_sync(0xFFFFFFFFu, v, off);
            if (lane + off < 32) v += o;
        }
        if (tid < 256 && lane == 0) wsum[warp] = v;
        __syncthreads();
        if (warp == 0 && lane < 8) {
            uint32_t w8 = wsum[lane];
            #pragma unroll
            for (int off = 1; off < 8; off <<= 1) {
                uint32_t o = __shfl_down_sync(0xFFu, w8, off, 8);
                if (lane + off < 8) w8 += o;
            }
            wsum[lane] = w8;
        }
        __syncthreads();
        if (tid < 256) {
            uint32_t cross = (warp < 7) ? wsum[warp + 1] : 0u;
            uint32_t S = v + cross;
            uint32_t Snext = S - h;
            if (S >= STHR && Snext < STHR) sh_bin = tid;
        }
        __syncthreads();
    }
    uint32_t pivot = (sh_bin >= 0) ? (gLo + ((uint32_t)sh_bin << 18)) : gLo;

    // ================= single full collect sweep =================
    for (int i0 = tid * 2; i0 < NV; i0 += NT * 2) {
        uint4 a = su4[i0];
        uint4 a2 = su4[i0 + 1];
        uint32_t ua[8] = { a.x, a.y, a.z, a.w, a2.x, a2.y, a2.z, a2.w };
        #pragma unroll
        for (int k = 0; k < 8; ++k) {
            if (ua[k] >= pivot) {
                int p = atomicAdd(&ccnt, 1);
                if (p < CAP)
                    ck64[p] = ((unsigned long long)ua[k] << 32)
                            | (uint32_t)~(uint32_t)(i0 * 4 + k);
            }
        }
    }
    __syncthreads();
    int nact = ccnt;
    bool ok = (nact <= CAP) && (nact >= TOPK || pivot == gLo);
    int used;

    if (ok) {
        used = nact;
    } else {
        // ============ exact fallback (rare): multi-level radix ============
        uint32_t fLo = gLo;
        int shift = 18, nbins = 256, cnt_above = 0, cnt_ge = 0, mode = 0, kr = 0;
        uint32_t fpivot = 0;
        for (;;) {
            if (tid < 256) hist[tid] = 0;
            if (tid == 0) sh_bf = -1;
            __syncthreads();
            for (int i = tid; i < N2; i += NT) {
                uint32_t u = su[i];
                if (u >= fLo) {
                    uint32_t r = (u - fLo) >> shift;
                    if (r < (uint32_t)nbins) atomicAdd(&hist[r], 1u);
                }
            }
            __syncthreads();
            uint32_t h = (tid < 256) ? hist[tid] : 0u;
            uint32_t v = h;
            #pragma unroll
            for (int off = 1; off < 32; off <<= 1) {
                uint32_t o = __shfl_down_sync(0xFFFFFFFFu, v, off);
                if (lane + off < 32) v += o;
            }
            if (tid < 256 && lane == 0) wsum[warp] = v;
            __syncthreads();
            if (warp == 0 && lane < 8) {
                uint32_t w8 = wsum[lane];
                #pragma unroll
                for (int off = 1; off < 8; off <<= 1) {
                    uint32_t o = __shfl_down_sync(0xFFu, w8, off, 8);
                    if (lane + off < 8) w8 += o;
                }
                wsum[lane] = w8;
            }
            __syncthreads();
            if (tid < 256 && h > 0) {
                uint32_t cross = (warp < 7) ? wsum[warp + 1] : 0u;
                int S = (int)(v + cross) + cnt_above;
                int Sa = S - (int)h;
                if (S >= TOPK && Sa < TOPK) { sh_bf = tid; sh_S = S; sh_Sa = Sa; }
            }
            __syncthreads();
            if (sh_bf < 0) {
                cnt_ge = cnt_above + (int)wsum[0];
                mode = 0;
                break;
            }
            fLo += ((uint32_t)sh_bf << shift);
            cnt_ge = sh_S;
            if (cnt_ge <= CAP) { mode = 0; break; }
            if (shift == 0) {
                fpivot = fLo; kr = TOPK - sh_Sa; cnt_above = sh_Sa; mode = 1;
                break;
            }
            cnt_above = sh_Sa;
            int ns = (shift >= 8) ? shift - 8 : 0;
            nbins = 1 << (shift - ns);
            shift = ns;
            __syncthreads();
        }
        __syncthreads();
        if (tid == 0) { ccnt = 0; eq_taken = 0; }
        __syncthreads();
        if (mode == 0) {
            for (int i = tid; i < N2; i += NT) {
                uint32_t u = su[i];
                if (u >= fLo) {
                    int p = atomicAdd(&ccnt, 1);
                    if (p < CAP)
                        ck64[p] = ((unsigned long long)u << 32) | (uint32_t)~(uint32_t)i;
                }
            }
            used = cnt_ge;
        } else {
            for (int i = tid; i < N2; i += NT) {
                uint32_t u = su[i];
                if (u > fpivot) {
                    int p = atomicAdd(&ccnt, 1);
                    if (p < CAP)
                        ck64[p] = ((unsigned long long)u << 32) | (uint32_t)~(uint32_t)i;
                }
            }
            __syncthreads();
            for (int base0 = 0; base0 < N2; base0 += NT) {
                int i = base0 + tid;
                bool eq = (i < N2) && (su[i] == fpivot);
                unsigned bal = __ballot_sync(0xFFFFFFFFu, eq);
                if (lane == 0) warp_cnt[warp] = __popc(bal);
                __syncthreads();
                int woff = 0;
                #pragma unroll
                for (int w = 0; w < NW; ++w) if (w < warp) woff += warp_cnt[w];
                int rank = eq_taken + woff + __popc(bal & ((1u << lane) - 1u));
                if (eq && rank < kr)
                    ck64[cnt_above + rank] = ((unsigned long long)fpivot << 32)
                                           | (uint32_t)~(uint32_t)i;
                __syncthreads();
                if (tid == 0) {
                    int tot = 0;
                    #pragma unroll
                    for (int w = 0; w < NW; ++w) tot += warp_cnt[w];
                    eq_taken += tot;
                }
                __syncthreads();
                if (eq_taken >= kr) break;
            }
            used = cnt_above + kr;
        }
    }
    __syncthreads();

    // ---- sort descending by (key, ~idx); rank r at slot P-1-r ----
    int P;
    if (used <= 512) {
        // fast path: P=512, 1 element/thread, shfl for j<=16
        P = 512;
        for (int s = used + tid; s < 512; s += NT) ck64[s] = 0ull;
        __syncthreads();
        unsigned long long e = ck64[tid];
        #pragma unroll
        for (int k = 2; k <= 32; k <<= 1) {
            #pragma unroll
            for (int j = k >> 1; j > 0; j >>= 1) {
                unsigned long long p = __shfl_xor_sync(0xFFFFFFFFu, e, j);
                bool takeMin = (((tid & j) == 0) == ((tid & k) == 0));
                e = takeMin ? my_u64min(e, p) : my_u64max(e, p);
            }
        }
        #pragma unroll
        for (int k = 64; k <= 512; k <<= 1) {
            for (int j = k >> 1; j >= 32; j >>= 1) {
                ck64[tid] = e; __syncthreads();
                unsigned long long p = ck64[tid ^ j]; __syncthreads();
                bool takeMin = (((tid & j) == 0) == ((tid & k) == 0));
                e = takeMin ? my_u64min(e, p) : my_u64max(e, p);
            }
            #pragma unroll
            for (int j = 16; j > 0; j >>= 1) {
                unsigned long long p = __shfl_xor_sync(0xFFFFFFFFu, e, j);
                bool takeMin = (((tid & j) == 0) == ((tid & k) == 0));
                e = takeMin ? my_u64min(e, p) : my_u64max(e, p);
            }
        }
        ck64[tid] = e;
        __syncthreads();
    } else {
        P = 1024;
        for (int s = used + tid; s < P; s += NT) ck64[s] = 0ull;
        __syncthreads();
        for (int k = 2; k <= P; k <<= 1) {
            for (int j = k >> 1; j > 0; j >>= 1) {
                for (int i = tid; i < P; i += NT) {
                    int ixj = i ^ j;
                    if (ixj > i) {
                        bool up = ((i & k) == 0);
                        unsigned long long a = ck64[i], bb2 = ck64[ixj];
                        if ((a > bb2) == up) { ck64[i] = bb2; ck64[ixj] = a; }
                    }
                }
                __syncthreads();
            }
        }
    }

    // ---- gather sorted top-200 scores + boxes + areas ----
    if (tid < TOPK) {
        if (tid < used) {
            unsigned long long v = ck64[P - 1 - tid];
            uint32_t key = (uint32_t)(v >> 32);
            uint32_t i = ~((uint32_t)v);
            cscore[tid] = o2f(key);
            float4 bp = ((const float4*)g_boxes)[(size_t)b * N2 + i];
            cb4[tid] = bp;
            carea[tid] = (bp.z - bp.x) * (bp.w - bp.y);
        } else {
            cscore[tid] = -1.0f;
            cb4[tid] = make_float4(0.f, 0.f, 0.f, 0.f);
            carea[tid] = 0.f;
        }
    }
    {
        bool v = (tid < TOPK) && (tid < used);
        uint32_t bal = __ballot_sync(0xFFFFFFFFu, v);
        if (lane == 0 && warp < KW) validw[warp] = bal;
    }
    __syncthreads();

    // ---- IoU > 0.45 bitmask, upper triangle only (i > j) ----
    // mapping: w = t / TOPK, j = t % TOPK  -> warp lanes share w, consecutive j
    // => cb4[i]/carea[i] reads broadcast, cb4[j] reads conflict-free
    for (int t = tid; t < TOPK * KW; t += NT) {
        int w = t / TOPK, j = t - w * TOPK;
        int i0 = w * 32;
        uint32_t m = 0;
        int istart = (j + 1 > i0) ? (j + 1) : i0;
        int iend = (i0 + 32 < TOPK) ? (i0 + 32) : TOPK;
        if (istart < iend) {
            float4 J = cb4[j];
            float ja = carea[j];
            #pragma unroll 4
            for (int i = istart; i < iend; ++i) {
                float4 I = cb4[i];
                float x1 = fmaxf(J.x, I.x);
                float y1 = fmaxf(J.y, I.y);
                float x2 = fminf(J.z, I.z);
                float y2 = fminf(J.w, I.w);
                float inter = fmaxf(x2 - x1, 0.0f) * fmaxf(y2 - y1, 0.0f);
                float un = ja + carea[i] - inter;
                float tt = fmaf(-0.45f, un, inter);     // inter - 0.45*union, 1 rounding
                float g = 5.96046448e-8f * un;          // 2^-24 * union guard band
                bool dec;
                if (tt > g) dec = true;
                else if (tt < -g) dec = false;
                else dec = (inter / un) > 0.45f;        // exact boundary fallback
                if (dec) m |= (1u << (i - i0));
            }
        }
        iou_mask[j * KW + w] = m;
    }
    __syncthreads();

    // ---- warp-cooperative greedy NMS (warp 0, lanes hold words) ----
    if (warp == 0) {
        uint32_t valid = (lane < KW) ? validw[lane] : 0u;
        uint32_t sup = 0u, kp = 0u;
        for (;;) {
            uint32_t rem = valid & ~sup;
            uint32_t has = __ballot_sync(0xFFFFFFFFu, rem != 0u);
            if (!has) break;
            int w0 = __ffs(has) - 1;
            uint32_t remw = __shfl_sync(0xFFFFFFFFu, rem, w0);
            int bit = __ffs(remw) - 1;
            int j = w0 * 32 + bit;
            if (lane == w0) { kp |= 1u << bit; sup |= 1u << bit; }
            uint32_t mr = (lane < KW) ? iou_mask[j * KW + lane] : 0u;
            sup |= mr;
        }
        if (lane < KW) keepw[lane] = kp;
    }
    __syncthreads();

    // ---- compacted writes ----
    if (tid < TOPK) {
        int w = tid >> 5, bit = tid & 31;
        if ((keepw[w] >> bit) & 1u) {
            int pos = __popc(keepw[w] & ((1u << bit) - 1u));
            for (int q = 0; q < w; ++q) pos += __popc(keepw[q]);
            float4 bp = cb4[tid];
            float* op = out + (((size_t)b * CC + c) * TOPK + pos) * 5;
            op[0] = cscore[tid];
            op[1] = bp.x; op[2] = bp.y;
            op[3] = bp.z; op[4] = bp.w;
        }
    }
}

// ---------------------------------------------------------------------------
extern "C" void kernel_launch(void* const* d_in, const int* in_sizes, int n_in,
                              void* d_out, int out_size) {
    const float* loc1  = (const float*)d_in[0];
    const float* conf1 = (const float*)d_in[1];
    const float* loc2  = (const float*)d_in[2];
    const float* conf2 = (const float*)d_in[3];
    const float* dbox  = (const float*)d_in[4];
    float* out = (float*)d_out;

    cudaMemsetAsync(d_out, 0, (size_t)out_size * sizeof(float), 0);

    int total = BB * NN;
    prep_kernel<<<(total + 255) / 256, 256>>>(loc1, conf1, loc2, conf2, dbox);

    dim3 grid(CC - 1, BB);
    nms_kernel<<<grid, NT>>>(out);
}

// round 16
// speedup vs baseline: 1.3415x; 1.3415x over previous
#include <cuda_runtime.h>
#include <cstdint>

#define BB 32
#define NN 8732
#define CC 21
#define N2 17464          // 2*NN
#define NV (N2/4)         // 4366 uint4s
#define TOPK 200
#define KW 7              // ceil(TOPK/32)
#define NT 512
#define NW (NT/32)
#define CAP 1024
#define STHR 40           // sampled-suffix threshold (-> ~320 est. candidates)

// scratch (allocation-free rule: device globals)
__device__ float    g_boxes[(size_t)BB * N2 * 4];   // [B][2N][4] xyxy
__device__ uint32_t g_keys[(size_t)BB * CC * N2];   // [B][C][2N] orderable keys (0 = below thresh)

__device__ __forceinline__ float o2f(uint32_t u) {
    return __uint_as_float(u & 0x7FFFFFFFu);
}
__device__ __forceinline__ unsigned long long my_u64min(unsigned long long a, unsigned long long b) {
    return a < b ? a : b;
}
__device__ __forceinline__ unsigned long long my_u64max(unsigned long long a, unsigned long long b) {
    return a > b ? a : b;
}

// ---------------------------------------------------------------------------
// Kernel 1: decode boxes (both views, view2 flipped) + softmax both views
// ---------------------------------------------------------------------------
__global__ __launch_bounds__(256) void prep_kernel(
    const float* __restrict__ loc1, const float* __restrict__ conf1,
    const float* __restrict__ loc2, const float* __restrict__ conf2,
    const float* __restrict__ dbox)
{
    int idx = blockIdx.x * 256 + threadIdx.x;
    if (idx >= BB * NN) return;
    int b = idx / NN, n = idx % NN;

    float4 d4 = ((const float4*)dbox)[n];
    float dcx = d4.x, dcy = d4.y, dw = d4.z, dh = d4.w;

    {
        float4 l = ((const float4*)loc1)[idx];
        float cx = dcx + (l.x * 0.1f) * dw;
        float cy = dcy + (l.y * 0.1f) * dh;
        float w = dw * expf(l.z * 0.2f);
        float h = dh * expf(l.w * 0.2f);
        float4 o;
        o.x = cx - w * 0.5f; o.y = cy - h * 0.5f;
        o.z = cx + w * 0.5f; o.w = cy + h * 0.5f;
        ((float4*)g_boxes)[(size_t)b * N2 + n] = o;
    }
    {
        float4 l = ((const float4*)loc2)[idx];
        float cx = dcx + (l.x * 0.1f) * dw;
        float cy = dcy + (l.y * 0.1f) * dh;
        float w = dw * expf(l.z * 0.2f);
        float h = dh * expf(l.w * 0.2f);
        float x1 = cx - w * 0.5f, x2 = cx + w * 0.5f;
        float4 o;
        o.x = 1.0f - x2; o.y = cy - h * 0.5f;
        o.z = 1.0f - x1; o.w = cy + h * 0.5f;
        ((float4*)g_boxes)[(size_t)b * N2 + NN + n] = o;
    }
    {
        const float* cf = conf1 + (size_t)idx * CC;
        float mx = cf[0];
        #pragma unroll
        for (int j = 1; j < CC; ++j) mx = fmaxf(mx, cf[j]);
        float e[CC]; float sum = 0.0f;
        #pragma unroll
        for (int j = 0; j < CC; ++j) { e[j] = expf(cf[j] - mx); sum += e[j]; }
        uint32_t* sb = g_keys + (size_t)b * CC * N2 + n;
        #pragma unroll
        for (int j = 1; j < CC; ++j) {        // class 0 never read
            float p = e[j] / sum;
            sb[(size_t)j * N2] = (p > 0.01f) ? (__float_as_uint(p) | 0x80000000u) : 0u;
        }
    }
    {
        const float* cf = conf2 + (size_t)idx * CC;
        float mx = cf[0];
        #pragma unroll
        for (int j = 1; j < CC; ++j) mx = fmaxf(mx, cf[j]);
        float e[CC]; float sum = 0.0f;
        #pragma unroll
        for (int j = 0; j < CC; ++j) { e[j] = expf(cf[j] - mx); sum += e[j]; }
        uint32_t* sb = g_keys + (size_t)b * CC * N2 + NN + n;
        #pragma unroll
        for (int j = 1; j < CC; ++j) {
            float p = e[j] / sum;
            sb[(size_t)j * N2] = (p > 0.01f) ? (__float_as_uint(p) | 0x80000000u) : 0u;
        }
    }
}

// ---------------------------------------------------------------------------
// Kernel 2: per (b, class>=1): top-200 (stable), NMS, compacted output
// ---------------------------------------------------------------------------
__global__ __launch_bounds__(NT, 4) void nms_kernel(float* __restrict__ out)
{
    const int c = blockIdx.x + 1;   // classes 1..20
    const int b = blockIdx.y;
    const int tid = threadIdx.x;
    const int lane = tid & 31, warp = tid >> 5;

    __shared__ uint32_t hist[256];
    __shared__ uint32_t wsum[8];
    __shared__ unsigned long long ck64[CAP];
    __shared__ float4 cb4[TOPK];
    __shared__ float4 cbg[KW][33];      // per-w-group staged copies, padded stride
    __shared__ float cscore[TOPK];
    __shared__ uint32_t iou_mask[TOPK * KW];
    __shared__ int sh_bin;
    __shared__ int ccnt, eq_taken;
    __shared__ int sh_bf, sh_S, sh_Sa;
    __shared__ int warp_cnt[NW];
    __shared__ uint32_t validw[KW], keepw[KW];

    const uint32_t* su = g_keys + ((size_t)b * CC + c) * N2;
    const uint4* su4 = (const uint4*)su;
    const uint32_t gLo = (__float_as_uint(0.01f) | 0x80000000u) + 1u;  // min valid key

    // ================= sampled histogram (1/8 stride) =================
    if (tid < 256) hist[tid] = 0;
    if (tid == 0) { sh_bin = -1; ccnt = 0; eq_taken = 0; }
    __syncthreads();
    for (int i = tid; i < N2 / 8; i += NT) {
        uint32_t u = su[i << 3];
        if (u >= gLo) {
            uint32_t r = (u - gLo) >> 18;
            if (r > 255u) r = 255u;
            atomicAdd(&hist[r], 1u);
        }
    }
    __syncthreads();
    {   // inclusive suffix scan of 256 bins
        uint32_t h = (tid < 256) ? hist[tid] : 0u;
        uint32_t v = h;
        #pragma unroll
        for (int off = 1; off < 32; off <<= 1) {
            uint32_t o = __shfl_down_sync(0xFFFFFFFFu, v, off);
            if (lane + off < 32) v += o;
        }
        if (tid < 256 && lane == 0) wsum[warp] = v;
        __syncthreads();
        if (warp == 0 && lane < 8) {
            uint32_t w8 = wsum[lane];
            #pragma unroll
            for (int off = 1; off < 8; off <<= 1) {
                uint32_t o = __shfl_down_sync(0xFFu, w8, off, 8);
                if (lane + off < 8) w8 += o;
            }
            wsum[lane] = w8;
        }
        __syncthreads();
        if (tid < 256) {
            uint32_t cross = (warp < 7) ? wsum[warp + 1] : 0u;
            uint32_t S = v + cross;
            uint32_t Snext = S - h;
            if (S >= STHR && Snext < STHR) sh_bin = tid;
        }
        __syncthreads();
    }
    uint32_t pivot = (sh_bin >= 0) ? (gLo + ((uint32_t)sh_bin << 18)) : gLo;

    // ================= single full collect sweep =================
    for (int i0 = tid * 2; i0 < NV; i0 += NT * 2) {
        uint4 a = su4[i0];
        uint4 a2 = su4[i0 + 1];
        uint32_t ua[8] = { a.x, a.y, a.z, a.w, a2.x, a2.y, a2.z, a2.w };
        #pragma unroll
        for (int k = 0; k < 8; ++k) {
            if (ua[k] >= pivot) {
                int p = atomicAdd(&ccnt, 1);
                if (p < CAP)
                    ck64[p] = ((unsigned long long)ua[k] << 32)
                            | (uint32_t)~(uint32_t)(i0 * 4 + k);
            }
        }
    }
    __syncthreads();
    int nact = ccnt;
    bool ok = (nact <= CAP) && (nact >= TOPK || pivot == gLo);
    int used;

    if (ok) {
        used = nact;
    } else {
        // ============ exact fallback (rare): multi-level radix ============
        uint32_t fLo = gLo;
        int shift = 18, nbins = 256, cnt_above = 0, cnt_ge = 0, mode = 0, kr = 0;
        uint32_t fpivot = 0;
        for (;;) {
            if (tid < 256) hist[tid] = 0;
            if (tid == 0) sh_bf = -1;
            __syncthreads();
            for (int i = tid; i < N2; i += NT) {
                uint32_t u = su[i];
                if (u >= fLo) {
                    uint32_t r = (u - fLo) >> shift;
                    if (r < (uint32_t)nbins) atomicAdd(&hist[r], 1u);
                }
            }
            __syncthreads();
            uint32_t h = (tid < 256) ? hist[tid] : 0u;
            uint32_t v = h;
            #pragma unroll
            for (int off = 1; off < 32; off <<= 1) {
                uint32_t o = __shfl_down_sync(0xFFFFFFFFu, v, off);
                if (lane + off < 32) v += o;
            }
            if (tid < 256 && lane == 0) wsum[warp] = v;
            __syncthreads();
            if (warp == 0 && lane < 8) {
                uint32_t w8 = wsum[lane];
                #pragma unroll
                for (int off = 1; off < 8; off <<= 1) {
                    uint32_t o = __shfl_down_sync(0xFFu, w8, off, 8);
                    if (lane + off < 8) w8 += o;
                }
                wsum[lane] = w8;
            }
            __syncthreads();
            if (tid < 256 && h > 0) {
                uint32_t cross = (warp < 7) ? wsum[warp + 1] : 0u;
                int S = (int)(v + cross) + cnt_above;
                int Sa = S - (int)h;
                if (S >= TOPK && Sa < TOPK) { sh_bf = tid; sh_S = S; sh_Sa = Sa; }
            }
            __syncthreads();
            if (sh_bf < 0) {
                cnt_ge = cnt_above + (int)wsum[0];
                mode = 0;
                break;
            }
            fLo += ((uint32_t)sh_bf << shift);
            cnt_ge = sh_S;
            if (cnt_ge <= CAP) { mode = 0; break; }
            if (shift == 0) {
                fpivot = fLo; kr = TOPK - sh_Sa; cnt_above = sh_Sa; mode = 1;
                break;
            }
            cnt_above = sh_Sa;
            int ns = (shift >= 8) ? shift - 8 : 0;
            nbins = 1 << (shift - ns);
            shift = ns;
            __syncthreads();
        }
        __syncthreads();
        if (tid == 0) { ccnt = 0; eq_taken = 0; }
        __syncthreads();
        if (mode == 0) {
            for (int i = tid; i < N2; i += NT) {
                uint32_t u = su[i];
                if (u >= fLo) {
                    int p = atomicAdd(&ccnt, 1);
                    if (p < CAP)
                        ck64[p] = ((unsigned long long)u << 32) | (uint32_t)~(uint32_t)i;
                }
            }
            used = cnt_ge;
        } else {
            for (int i = tid; i < N2; i += NT) {
                uint32_t u = su[i];
                if (u > fpivot) {
                    int p = atomicAdd(&ccnt, 1);
                    if (p < CAP)
                        ck64[p] = ((unsigned long long)u << 32) | (uint32_t)~(uint32_t)i;
                }
            }
            __syncthreads();
            for (int base0 = 0; base0 < N2; base0 += NT) {
                int i = base0 + tid;
                bool eq = (i < N2) && (su[i] == fpivot);
                unsigned bal = __ballot_sync(0xFFFFFFFFu, eq);
                if (lane == 0) warp_cnt[warp] = __popc(bal);
                __syncthreads();
                int woff = 0;
                #pragma unroll
                for (int w = 0; w < NW; ++w) if (w < warp) woff += warp_cnt[w];
                int rank = eq_taken + woff + __popc(bal & ((1u << lane) - 1u));
                if (eq && rank < kr)
                    ck64[cnt_above + rank] = ((unsigned long long)fpivot << 32)
                                           | (uint32_t)~(uint32_t)i;
                __syncthreads();
                if (tid == 0) {
                    int tot = 0;
                    #pragma unroll
                    for (int w = 0; w < NW; ++w) tot += warp_cnt[w];
                    eq_taken += tot;
                }
                __syncthreads();
                if (eq_taken >= kr) break;
            }
            used = cnt_above + kr;
        }
    }
    __syncthreads();

    // ---- sort descending by (key, ~idx); rank r at slot P-1-r ----
    int P;
    if (used <= 512) {
        // fast path: P=512, 1 element/thread, shfl for j<=16
        P = 512;
        for (int s = used + tid; s < 512; s += NT) ck64[s] = 0ull;
        __syncthreads();
        unsigned long long e = ck64[tid];
        #pragma unroll
        for (int k = 2; k <= 32; k <<= 1) {
            #pragma unroll
            for (int j = k >> 1; j > 0; j >>= 1) {
                unsigned long long p = __shfl_xor_sync(0xFFFFFFFFu, e, j);
                bool takeMin = (((tid & j) == 0) == ((tid & k) == 0));
                e = takeMin ? my_u64min(e, p) : my_u64max(e, p);
            }
        }
        #pragma unroll
        for (int k = 64; k <= 512; k <<= 1) {
            for (int j = k >> 1; j >= 32; j >>= 1) {
                ck64[tid] = e; __syncthreads();
                unsigned long long p = ck64[tid ^ j]; __syncthreads();
                bool takeMin = (((tid & j) == 0) == ((tid & k) == 0));
                e = takeMin ? my_u64min(e, p) : my_u64max(e, p);
            }
            #pragma unroll
            for (int j = 16; j > 0; j >>= 1) {
                unsigned long long p = __shfl_xor_sync(0xFFFFFFFFu, e, j);
                bool takeMin = (((tid & j) == 0) == ((tid & k) == 0));
                e = takeMin ? my_u64min(e, p) : my_u64max(e, p);
            }
        }
        ck64[tid] = e;
        __syncthreads();
    } else {
        P = 1024;
        for (int s = used + tid; s < P; s += NT) ck64[s] = 0ull;
        __syncthreads();
        for (int k = 2; k <= P; k <<= 1) {
            for (int j = k >> 1; j > 0; j >>= 1) {
                for (int i = tid; i < P; i += NT) {
                    int ixj = i ^ j;
                    if (ixj > i) {
                        bool up = ((i & k) == 0);
                        unsigned long long a = ck64[i], bb2 = ck64[ixj];
                        if ((a > bb2) == up) { ck64[i] = bb2; ck64[ixj] = a; }
                    }
                }
                __syncthreads();
            }
        }
    }

    // ---- gather sorted top-200 scores + boxes (float4 AoS) ----
    if (tid < TOPK) {
        if (tid < used) {
            unsigned long long v = ck64[P - 1 - tid];
            uint32_t key = (uint32_t)(v >> 32);
            uint32_t i = ~((uint32_t)v);
            cscore[tid] = o2f(key);
            cb4[tid] = ((const float4*)g_boxes)[(size_t)b * N2 + i];
        } else {
            cscore[tid] = -1.0f;
            cb4[tid] = make_float4(0.f, 0.f, 0.f, 0.f);
        }
    }
    {
        bool v = (tid < TOPK) && (tid < used);
        uint32_t bal = __ballot_sync(0xFFFFFFFFu, v);
        if (lane == 0 && warp < KW) validw[warp] = bal;
    }
    __syncthreads();

    // ---- stage per-w-group box copies (bank-offset by padding) ----
    for (int t = tid; t < KW * 32; t += NT) {
        int w = t >> 5, q = t & 31;
        int i = w * 32 + q;
        cbg[w][q] = (i < TOPK) ? cb4[i] : make_float4(0.f, 0.f, 0.f, 0.f);
    }
    __syncthreads();

    // ---- IoU > 0.45 bitmask, upper triangle only (i > j) ----
    // R11 mapping/structure; reads from staged conflict-free copies
    for (int t = tid; t < TOPK * KW; t += NT) {
        int j = t / KW, w = t - j * KW;
        int i0 = w * 32;
        uint32_t m = 0;
        if (i0 + 31 > j) {
            float4 J = cb4[j];
            float ja = (J.z - J.x) * (J.w - J.y);
            int qs = (j >= i0) ? (j - i0 + 1) : 0;
            #pragma unroll 4
            for (int q = qs; q < 32; ++q) {
                int i = i0 + q;
                if (i >= TOPK) break;
                float4 I = cbg[w][q];
                float x1 = fmaxf(J.x, I.x);
                float y1 = fmaxf(J.y, I.y);
                float x2 = fminf(J.z, I.z);
                float y2 = fminf(J.w, I.w);
                float inter = fmaxf(x2 - x1, 0.0f) * fmaxf(y2 - y1, 0.0f);
                float ia = (I.z - I.x) * (I.w - I.y);
                float un = ja + ia - inter;
                float tt = fmaf(-0.45f, un, inter);     // inter - 0.45*union, 1 rounding
                float g = 5.96046448e-8f * un;          // 2^-24 * union guard band
                bool dec;
                if (tt > g) dec = true;
                else if (tt < -g) dec = false;
                else dec = (inter / un) > 0.45f;        // exact boundary fallback
                if (dec) m |= (1u << q);
            }
        }
        iou_mask[j * KW + w] = m;
    }
    __syncthreads();

    // ---- warp-cooperative greedy NMS (warp 0, lanes hold words) ----
    if (warp == 0) {
        uint32_t valid = (lane < KW) ? validw[lane] : 0u;
        uint32_t sup = 0u, kp = 0u;
        for (;;) {
            uint32_t rem = valid & ~sup;
            uint32_t has = __ballot_sync(0xFFFFFFFFu, rem != 0u);
            if (!has) break;
            int w0 = __ffs(has) - 1;
            uint32_t remw = __shfl_sync(0xFFFFFFFFu, rem, w0);
            int bit = __ffs(remw) - 1;
            int j = w0 * 32 + bit;
            if (lane == w0) { kp |= 1u << bit; sup |= 1u << bit; }
            uint32_t mr = (lane < KW) ? iou_mask[j * KW + lane] : 0u;
            sup |= mr;
        }
        if (lane < KW) keepw[lane] = kp;
    }
    __syncthreads();

    // ---- compacted writes ----
    if (tid < TOPK) {
        int w = tid >> 5, bit = tid & 31;
        if ((keepw[w] >> bit) & 1u) {
            int pos = __popc(keepw[w] & ((1u << bit) - 1u));
            for (int q = 0; q < w; ++q) pos += __popc(keepw[q]);
            float4 bp = cb4[tid];
            float* op = out + (((size_t)b * CC + c) * TOPK + pos) * 5;
            op[0] = cscore[tid];
            op[1] = bp.x; op[2] = bp.y;
            op[3] = bp.z; op[4] = bp.w;
        }
    }
}

// ---------------------------------------------------------------------------
extern "C" void kernel_launch(void* const* d_in, const int* in_sizes, int n_in,
                              void* d_out, int out_size) {
    const float* loc1  = (const float*)d_in[0];
    const float* conf1 = (const float*)d_in[1];
    const float* loc2  = (const float*)d_in[2];
    const float* conf2 = (const float*)d_in[3];
    const float* dbox  = (const float*)d_in[4];
    float* out = (float*)d_out;

    cudaMemsetAsync(d_out, 0, (size_t)out_size * sizeof(float), 0);

    int total = BB * NN;
    prep_kernel<<<(total + 255) / 256, 256>>>(loc1, conf1, loc2, conf2, dbox);

    dim3 grid(CC - 1, BB);
    nms_kernel<<<grid, NT>>>(out);
}